// round 12
// baseline (speedup 1.0000x reference)
#include <cuda_runtime.h>
#include <cuda_bf16.h>
#include <cstdint>

// Problem: B=1, N=4096, H=16, D=64, C=1024
static constexpr int SEQ   = 4096;
static constexpr int CDIM  = 1024;
static constexpr int QKV3  = 3 * CDIM;   // 3072
static constexpr int HEADS = 16;
// Q is pre-scaled by SCALE*log2(e) so attention scores are in log2 domain.
static constexpr float SCALE_LOG2E = 0.125f * 1.4426950408889634f;

// ---------------------------------------------------------------------------
// Scratch (device globals; no allocations allowed)
// ---------------------------------------------------------------------------
__device__ float g_qkv [SEQ * QKV3];      // fp32 qkv (only V third written now)

__device__ __nv_bfloat16 g_xh[SEQ * CDIM],  g_xl[SEQ * CDIM];
__device__ __nv_bfloat16 g_wqh[QKV3 * CDIM], g_wql[QKV3 * CDIM];
__device__ __nv_bfloat16 g_wph[CDIM * CDIM], g_wpl[CDIM * CDIM];
// per-head contiguous: [h][n][64]
__device__ __nv_bfloat16 g_qh[HEADS * SEQ * 64], g_ql[HEADS * SEQ * 64];
__device__ __nv_bfloat16 g_kh[HEADS * SEQ * 64], g_kl[HEADS * SEQ * 64];
// V transposed: [h][d][n]
__device__ __nv_bfloat16 g_vth[HEADS * 64 * SEQ], g_vtl[HEADS * 64 * SEQ];
// attention output split (written directly by attn epilogue)
__device__ __nv_bfloat16 g_ah[SEQ * CDIM], g_al[SEQ * CDIM];

// ---------------------------------------------------------------------------
// Helpers
// ---------------------------------------------------------------------------
__device__ __forceinline__ void mma16816(float* c, const unsigned* a, const unsigned* b)
{
    asm volatile(
        "mma.sync.aligned.m16n8k16.row.col.f32.bf16.bf16.f32 "
        "{%0,%1,%2,%3}, {%4,%5,%6,%7}, {%8,%9}, {%0,%1,%2,%3};"
        : "+f"(c[0]), "+f"(c[1]), "+f"(c[2]), "+f"(c[3])
        : "r"(a[0]), "r"(a[1]), "r"(a[2]), "r"(a[3]), "r"(b[0]), "r"(b[1]));
}

__device__ __forceinline__ unsigned pack2(float x, float y)
{
    unsigned lo = (unsigned)__bfloat16_as_ushort(__float2bfloat16_rn(x));
    unsigned hi = (unsigned)__bfloat16_as_ushort(__float2bfloat16_rn(y));
    return lo | (hi << 16);
}

__device__ __forceinline__ void split1(float x, unsigned short& h, unsigned short& l)
{
    __nv_bfloat16 hb = __float2bfloat16_rn(x);
    __nv_bfloat16 lb = __float2bfloat16_rn(x - __bfloat162float(hb));
    h = __bfloat16_as_ushort(hb);
    l = __bfloat16_as_ushort(lb);
}

// split a pair of fp32 and store packed bf16x2 into hi/lo arrays at idx (even)
__device__ __forceinline__ void store_split2(__nv_bfloat16* hi, __nv_bfloat16* lo,
                                             size_t idx, float a, float b)
{
    unsigned short h0, l0, h1, l1;
    split1(a, h0, l0); split1(b, h1, l1);
    *reinterpret_cast<unsigned*>(&hi[idx]) = (unsigned)h0 | ((unsigned)h1 << 16);
    *reinterpret_cast<unsigned*>(&lo[idx]) = (unsigned)l0 | ((unsigned)l1 << 16);
}

__device__ __forceinline__ void cp16(void* s, const void* g)
{
    unsigned sa = (unsigned)__cvta_generic_to_shared(s);
    asm volatile("cp.async.cg.shared.global [%0], [%1], 16;" :: "r"(sa), "l"(g));
}
__device__ __forceinline__ void cp_commit()
{
    asm volatile("cp.async.commit_group;");
}
__device__ __forceinline__ void cp_wait_all()
{
    asm volatile("cp.async.wait_group 0;");
}

// ---------------------------------------------------------------------------
// Elementwise hi/lo split, 4 floats per thread
// ---------------------------------------------------------------------------
__global__ void split_plain(const float* __restrict__ in,
                            __nv_bfloat16* __restrict__ hi,
                            __nv_bfloat16* __restrict__ lo, int n4)
{
    int i = blockIdx.x * blockDim.x + threadIdx.x;
    if (i >= n4) return;
    float4 v = reinterpret_cast<const float4*>(in)[i];
    unsigned short h0,h1,h2,h3,l0,l1,l2,l3;
    split1(v.x,h0,l0); split1(v.y,h1,l1); split1(v.z,h2,l2); split1(v.w,h3,l3);
    uint2 uh, ul;
    uh.x = (unsigned)h0 | ((unsigned)h1 << 16); uh.y = (unsigned)h2 | ((unsigned)h3 << 16);
    ul.x = (unsigned)l0 | ((unsigned)l1 << 16); ul.y = (unsigned)l2 | ((unsigned)l3 << 16);
    reinterpret_cast<uint2*>(hi)[i] = uh;
    reinterpret_cast<uint2*>(lo)[i] = ul;
}

// V: qkv fp32 (V third) -> transposed hi/lo [h][d][n]
__global__ void split_v_trans(const float* __restrict__ qkv,
                              __nv_bfloat16* __restrict__ vth,
                              __nv_bfloat16* __restrict__ vtl)
{
    __shared__ float tile[64][65];
    const int h  = blockIdx.y;
    const int nb = blockIdx.x * 64;
    const int tid = threadIdx.x;
#pragma unroll
    for (int it = 0; it < 4; it++) {
        int slot = tid + it * 256;          // 0..1023
        int row  = slot >> 4;               // n within tile
        int d4   = (slot & 15) * 4;
        float4 v = *reinterpret_cast<const float4*>(
            &qkv[(size_t)(nb + row) * QKV3 + 2 * CDIM + h * 64 + d4]);
        tile[row][d4+0] = v.x; tile[row][d4+1] = v.y;
        tile[row][d4+2] = v.z; tile[row][d4+3] = v.w;
    }
    __syncthreads();
    const int d  = tid >> 2;
    const int n0 = (tid & 3) * 16;
    size_t base = ((size_t)h << 18) + (size_t)d * SEQ + nb + n0;
#pragma unroll
    for (int seg = 0; seg < 4; seg++) {
        unsigned short hh[4], ll[4];
#pragma unroll
        for (int j = 0; j < 4; j++) split1(tile[n0 + seg*4 + j][d], hh[j], ll[j]);
        uint2 u;
        u.x = (unsigned)hh[0] | ((unsigned)hh[1]<<16); u.y = (unsigned)hh[2] | ((unsigned)hh[3]<<16);
        *reinterpret_cast<uint2*>(&vth[base + seg*4]) = u;
        u.x = (unsigned)ll[0] | ((unsigned)ll[1]<<16); u.y = (unsigned)ll[2] | ((unsigned)ll[3]<<16);
        *reinterpret_cast<uint2*>(&vtl[base + seg*4]) = u;
    }
}

// ---------------------------------------------------------------------------
// Split-bf16 tensor-core GEMM with 2-stage cp.async pipeline.
// C[M,N] = A[M,K] * B[N,K]^T. 128x128 block, 8 warps (2m x 4n), warp 64x32,
// K-tile 32, smem row stride 40 bf16.
// MODE 0 (QKV): fused epilogue — Q cols (pre-scaled by SCALE*log2e) ->
//               qh/ql [h][n][64]; K cols -> kh/kl; V cols -> fp32 qkv buffer.
// MODE 1 (proj): bias add, fp32 out.
// ---------------------------------------------------------------------------
static constexpr int G_STG = 4 * 128 * 40;   // bf16 per stage (20480)

template <int MODE>
__global__ __launch_bounds__(256, 2) void gemm_nt_mma(
    const __nv_bfloat16* __restrict__ Ah, const __nv_bfloat16* __restrict__ Al,
    const __nv_bfloat16* __restrict__ Bh, const __nv_bfloat16* __restrict__ Bl,
    const float* __restrict__ bias, float* __restrict__ C,
    __nv_bfloat16* __restrict__ Qh, __nv_bfloat16* __restrict__ Ql,
    __nv_bfloat16* __restrict__ Kh, __nv_bfloat16* __restrict__ Kl,
    int M, int N, int K)
{
    extern __shared__ __nv_bfloat16 smem[];

    const int bm = blockIdx.y * 128, bn = blockIdx.x * 128;
    const int tid = threadIdx.x;
    const int warp = tid >> 5, lane = tid & 31;
    const int wm = warp >> 2, wn = warp & 3;      // 2 x 4
    const int g = lane >> 2, t = lane & 3;

    float acc[4][4][4];
#pragma unroll
    for (int mi = 0; mi < 4; mi++)
#pragma unroll
        for (int ni = 0; ni < 4; ni++)
#pragma unroll
            for (int r = 0; r < 4; r++) acc[mi][ni][r] = 0.f;

    auto load_tile = [&](int st, int k0) {
        __nv_bfloat16* sAh = smem + st * G_STG;
        __nv_bfloat16* sAl = sAh + 128*40;
        __nv_bfloat16* sBh = sAh + 2*128*40;
        __nv_bfloat16* sBl = sAh + 3*128*40;
#pragma unroll
        for (int it = 0; it < 2; it++) {
            int slot = tid + it * 256;            // 0..511
            int row  = slot >> 2;                 // 0..127
            int kc   = (slot & 3) * 8;            // 0,8,16,24
            size_t ga = (size_t)(bm + row) * K + k0 + kc;
            size_t gb = (size_t)(bn + row) * K + k0 + kc;
            cp16(&sAh[row*40 + kc], &Ah[ga]);
            cp16(&sAl[row*40 + kc], &Al[ga]);
            cp16(&sBh[row*40 + kc], &Bh[gb]);
            cp16(&sBl[row*40 + kc], &Bl[gb]);
        }
        cp_commit();
    };

    load_tile(0, 0);
    int stage = 0;

    for (int k0 = 0; k0 < K; k0 += 32) {
        cp_wait_all();
        __syncthreads();
        if (k0 + 32 < K) load_tile(stage ^ 1, k0 + 32);

        const __nv_bfloat16* sAh = smem + stage * G_STG;
        const __nv_bfloat16* sAl = sAh + 128*40;
        const __nv_bfloat16* sBh = sAh + 2*128*40;
        const __nv_bfloat16* sBl = sAh + 3*128*40;

#pragma unroll
        for (int kk = 0; kk < 32; kk += 16) {
            unsigned bh[4][2], bl[4][2];
#pragma unroll
            for (int ni = 0; ni < 4; ni++) {
                int base = (wn*32 + ni*8 + g) * 40 + kk + 2*t;
                bh[ni][0] = *reinterpret_cast<const unsigned*>(&sBh[base]);
                bh[ni][1] = *reinterpret_cast<const unsigned*>(&sBh[base + 8]);
                bl[ni][0] = *reinterpret_cast<const unsigned*>(&sBl[base]);
                bl[ni][1] = *reinterpret_cast<const unsigned*>(&sBl[base + 8]);
            }
#pragma unroll
            for (int mi = 0; mi < 4; mi++) {
                int base = (wm*64 + mi*16 + g) * 40 + kk + 2*t;
                unsigned ah[4], al[4];
                ah[0] = *reinterpret_cast<const unsigned*>(&sAh[base]);
                ah[1] = *reinterpret_cast<const unsigned*>(&sAh[base + 8*40]);
                ah[2] = *reinterpret_cast<const unsigned*>(&sAh[base + 8]);
                ah[3] = *reinterpret_cast<const unsigned*>(&sAh[base + 8*40 + 8]);
                al[0] = *reinterpret_cast<const unsigned*>(&sAl[base]);
                al[1] = *reinterpret_cast<const unsigned*>(&sAl[base + 8*40]);
                al[2] = *reinterpret_cast<const unsigned*>(&sAl[base + 8]);
                al[3] = *reinterpret_cast<const unsigned*>(&sAl[base + 8*40 + 8]);
#pragma unroll
                for (int ni = 0; ni < 4; ni++) {
                    mma16816(acc[mi][ni], ah, bh[ni]);
                    mma16816(acc[mi][ni], ah, bl[ni]);
                    mma16816(acc[mi][ni], al, bh[ni]);
                }
            }
        }
        stage ^= 1;
    }

    // ---- epilogue ----
    if (MODE == 1) {
        // proj: bias + fp32 out
#pragma unroll
        for (int mi = 0; mi < 4; mi++) {
            int r0 = bm + wm*64 + mi*16 + g;
#pragma unroll
            for (int ni = 0; ni < 4; ni++) {
                int col = bn + wn*32 + ni*8 + 2*t;
                float b0 = bias[col], b1 = bias[col + 1];
                float2 v0 = {acc[mi][ni][0] + b0, acc[mi][ni][1] + b1};
                float2 v1 = {acc[mi][ni][2] + b0, acc[mi][ni][3] + b1};
                *reinterpret_cast<float2*>(&C[(size_t)r0 * N + col])     = v0;
                *reinterpret_cast<float2*>(&C[(size_t)(r0+8) * N + col]) = v1;
            }
        }
    } else {
        // QKV fused epilogue (bn uniform per block: Q, K or V region)
        if (bn < 2 * CDIM) {
            const bool isQ = (bn < CDIM);
            __nv_bfloat16* dh = isQ ? Qh : Kh;
            __nv_bfloat16* dl = isQ ? Ql : Kl;
            const float sc = isQ ? SCALE_LOG2E : 1.0f;
#pragma unroll
            for (int mi = 0; mi < 4; mi++) {
                int r0 = bm + wm*64 + mi*16 + g;
#pragma unroll
                for (int ni = 0; ni < 4; ni++) {
                    int cg  = bn + wn*32 + ni*8 + 2*t;           // global col
                    int cc  = isQ ? cg : (cg - CDIM);            // 0..1023
                    int h   = cc >> 6, d = cc & 63;
                    size_t o0 = ((size_t)h << 18) + (size_t)r0 * 64 + d;
                    size_t o1 = o0 + 8 * 64;
                    store_split2(dh, dl, o0, acc[mi][ni][0] * sc, acc[mi][ni][1] * sc);
                    store_split2(dh, dl, o1, acc[mi][ni][2] * sc, acc[mi][ni][3] * sc);
                }
            }
        } else {
            // V region: fp32 write for split_v_trans
#pragma unroll
            for (int mi = 0; mi < 4; mi++) {
                int r0 = bm + wm*64 + mi*16 + g;
#pragma unroll
                for (int ni = 0; ni < 4; ni++) {
                    int col = bn + wn*32 + ni*8 + 2*t;
                    float2 v0 = {acc[mi][ni][0], acc[mi][ni][1]};
                    float2 v1 = {acc[mi][ni][2], acc[mi][ni][3]};
                    *reinterpret_cast<float2*>(&C[(size_t)r0 * N + col])     = v0;
                    *reinterpret_cast<float2*>(&C[(size_t)(r0+8) * N + col]) = v1;
                }
            }
        }
    }
}

// ---------------------------------------------------------------------------
// Flash attention, split-bf16 mma, 2-stage cp.async pipeline on K/V tiles.
// Scores arrive in log2 domain (Q pre-scaled by SCALE*log2e) -> exp2f softmax.
// Block = 128 q-rows x 1 head, 8 warps, each warp owns 16 full rows.
// Epilogue writes hi/lo bf16 directly (fused split for the proj GEMM).
// ---------------------------------------------------------------------------
static constexpr int A_Q   = 2 * 128 * 72;   // Q hi+lo bf16 (18432)
static constexpr int A_STG = 4 * 64 * 72;    // K/V hi+lo per stage (18432)

__global__ __launch_bounds__(256, 2) void attn_mma(
    const __nv_bfloat16* __restrict__ Qh, const __nv_bfloat16* __restrict__ Ql,
    const __nv_bfloat16* __restrict__ Kh, const __nv_bfloat16* __restrict__ Kl,
    const __nv_bfloat16* __restrict__ Vth, const __nv_bfloat16* __restrict__ Vtl,
    __nv_bfloat16* __restrict__ outh, __nv_bfloat16* __restrict__ outl)
{
    extern __shared__ __nv_bfloat16 sm[];
    __nv_bfloat16* sQh = sm;               // [128][72]
    __nv_bfloat16* sQl = sm + 128*72;
    __nv_bfloat16* kvb = sm + A_Q;

    const int qi = gridDim.x - 1 - blockIdx.x;   // reverse for causal balance
    const int h  = blockIdx.y;
    const int qbase = qi * 128;
    const int tid = threadIdx.x;
    const int warp = tid >> 5, lane = tid & 31;
    const int g = lane >> 2, t = lane & 3;
    const size_t hoff = (size_t)h << 18;         // h * 4096 * 64

    auto load_kv = [&](int st, int jt) {
        __nv_bfloat16* sKh = kvb + st * A_STG;
        __nv_bfloat16* sKl = sKh + 64*72;
        __nv_bfloat16* sVh = sKh + 2*64*72;
        __nv_bfloat16* sVl = sKh + 3*64*72;
        const int kb = jt * 64;
#pragma unroll
        for (int it = 0; it < 2; it++) {
            int slot = tid + it * 256;    // 0..511
            int row  = slot >> 3;         // 0..63
            int kc   = (slot & 7) * 8;
            size_t gk = hoff + (size_t)(kb + row) * 64 + kc;
            size_t gv = hoff + (size_t)row * SEQ + kb + kc;
            cp16(&sKh[row*72 + kc], &Kh[gk]);
            cp16(&sKl[row*72 + kc], &Kl[gk]);
            cp16(&sVh[row*72 + kc], &Vth[gv]);
            cp16(&sVl[row*72 + kc], &Vtl[gv]);
        }
        cp_commit();
    };

#pragma unroll
    for (int it = 0; it < 4; it++) {
        int slot = tid + it * 256;        // 0..1023
        int row  = slot >> 3;             // 0..127
        int kc   = (slot & 7) * 8;        // 0..56
        size_t gq = hoff + (size_t)(qbase + row) * 64 + kc;
        cp16(&sQh[row*72 + kc], &Qh[gq]);
        cp16(&sQl[row*72 + kc], &Ql[gq]);
    }
    cp_commit();
    load_kv(0, 0);
    int stage = 0;

    float o[8][4];
#pragma unroll
    for (int j = 0; j < 8; j++)
#pragma unroll
        for (int r = 0; r < 4; r++) o[j][r] = 0.f;
    float m0 = -1e30f, m1 = -1e30f, l0 = 0.f, l1 = 0.f;

    const int row0 = qbase + warp*16 + g;
    const int row1 = row0 + 8;
    const int jt_max = 2*qi + 1;

    for (int jt = 0; jt <= jt_max; jt++) {
        cp_wait_all();
        __syncthreads();
        if (jt < jt_max) load_kv(stage ^ 1, jt + 1);

        const __nv_bfloat16* sKh = kvb + stage * A_STG;
        const __nv_bfloat16* sKl = sKh + 64*72;
        const __nv_bfloat16* sVh = sKh + 2*64*72;
        const __nv_bfloat16* sVl = sKh + 3*64*72;
        const int kb = jt * 64;

        // ---- S = Q K^T (already in log2 units) ----
        float s[8][4];
#pragma unroll
        for (int j = 0; j < 8; j++)
#pragma unroll
            for (int r = 0; r < 4; r++) s[j][r] = 0.f;

#pragma unroll
        for (int kc = 0; kc < 64; kc += 16) {
            int ab = (warp*16 + g) * 72 + kc + 2*t;
            unsigned qh[4], ql[4];
            qh[0] = *reinterpret_cast<const unsigned*>(&sQh[ab]);
            qh[1] = *reinterpret_cast<const unsigned*>(&sQh[ab + 8*72]);
            qh[2] = *reinterpret_cast<const unsigned*>(&sQh[ab + 8]);
            qh[3] = *reinterpret_cast<const unsigned*>(&sQh[ab + 8*72 + 8]);
            ql[0] = *reinterpret_cast<const unsigned*>(&sQl[ab]);
            ql[1] = *reinterpret_cast<const unsigned*>(&sQl[ab + 8*72]);
            ql[2] = *reinterpret_cast<const unsigned*>(&sQl[ab + 8]);
            ql[3] = *reinterpret_cast<const unsigned*>(&sQl[ab + 8*72 + 8]);
#pragma unroll
            for (int j = 0; j < 8; j++) {
                int bb = (j*8 + g) * 72 + kc + 2*t;
                unsigned kh[2], kl[2];
                kh[0] = *reinterpret_cast<const unsigned*>(&sKh[bb]);
                kh[1] = *reinterpret_cast<const unsigned*>(&sKh[bb + 8]);
                kl[0] = *reinterpret_cast<const unsigned*>(&sKl[bb]);
                kl[1] = *reinterpret_cast<const unsigned*>(&sKl[bb + 8]);
                mma16816(s[j], qh, kh);
                mma16816(s[j], qh, kl);
                mma16816(s[j], ql, kh);
            }
        }

        // ---- causal mask (no scale needed; folded into Q) ----
        const bool need_mask = (jt >= 2*qi);
        if (need_mask) {
#pragma unroll
            for (int j = 0; j < 8; j++) {
                int c0 = kb + j*8 + 2*t;
                if (c0     > row0) s[j][0] = -1e30f;
                if (c0 + 1 > row0) s[j][1] = -1e30f;
                if (c0     > row1) s[j][2] = -1e30f;
                if (c0 + 1 > row1) s[j][3] = -1e30f;
            }
        }

        // ---- online softmax (base-2) ----
        float mx0 = -1e30f, mx1 = -1e30f;
#pragma unroll
        for (int j = 0; j < 8; j++) {
            mx0 = fmaxf(mx0, fmaxf(s[j][0], s[j][1]));
            mx1 = fmaxf(mx1, fmaxf(s[j][2], s[j][3]));
        }
        mx0 = fmaxf(mx0, __shfl_xor_sync(0xffffffffu, mx0, 1));
        mx0 = fmaxf(mx0, __shfl_xor_sync(0xffffffffu, mx0, 2));
        mx1 = fmaxf(mx1, __shfl_xor_sync(0xffffffffu, mx1, 1));
        mx1 = fmaxf(mx1, __shfl_xor_sync(0xffffffffu, mx1, 2));

        const float mn0 = fmaxf(m0, mx0), mn1 = fmaxf(m1, mx1);
        const float a0 = exp2f(m0 - mn0), a1 = exp2f(m1 - mn1);
        float sum0 = 0.f, sum1 = 0.f;
#pragma unroll
        for (int j = 0; j < 8; j++) {
            s[j][0] = exp2f(s[j][0] - mn0); sum0 += s[j][0];
            s[j][1] = exp2f(s[j][1] - mn0); sum0 += s[j][1];
            s[j][2] = exp2f(s[j][2] - mn1); sum1 += s[j][2];
            s[j][3] = exp2f(s[j][3] - mn1); sum1 += s[j][3];
        }
        sum0 += __shfl_xor_sync(0xffffffffu, sum0, 1);
        sum0 += __shfl_xor_sync(0xffffffffu, sum0, 2);
        sum1 += __shfl_xor_sync(0xffffffffu, sum1, 1);
        sum1 += __shfl_xor_sync(0xffffffffu, sum1, 2);
        l0 = l0 * a0 + sum0;  m0 = mn0;
        l1 = l1 * a1 + sum1;  m1 = mn1;
#pragma unroll
        for (int j = 0; j < 8; j++) {
            o[j][0] *= a0; o[j][1] *= a0;
            o[j][2] *= a1; o[j][3] *= a1;
        }

        // ---- O += P V : P frags straight from S registers ----
#pragma unroll
        for (int kc = 0; kc < 4; kc++) {              // 16 keys each
            const int j0 = 2*kc;
            unsigned ph[4], pl[4];
            ph[0] = pack2(s[j0][0],   s[j0][1]);
            ph[1] = pack2(s[j0][2],   s[j0][3]);
            ph[2] = pack2(s[j0+1][0], s[j0+1][1]);
            ph[3] = pack2(s[j0+1][2], s[j0+1][3]);
            {
                float r, r2;
                r  = s[j0][0] - __bfloat162float(__ushort_as_bfloat16((unsigned short)(ph[0] & 0xffff)));
                r2 = s[j0][1] - __bfloat162float(__ushort_as_bfloat16((unsigned short)(ph[0] >> 16)));
                pl[0] = pack2(r, r2);
                r  = s[j0][2] - __bfloat162float(__ushort_as_bfloat16((unsigned short)(ph[1] & 0xffff)));
                r2 = s[j0][3] - __bfloat162float(__ushort_as_bfloat16((unsigned short)(ph[1] >> 16)));
                pl[1] = pack2(r, r2);
                r  = s[j0+1][0] - __bfloat162float(__ushort_as_bfloat16((unsigned short)(ph[2] & 0xffff)));
                r2 = s[j0+1][1] - __bfloat162float(__ushort_as_bfloat16((unsigned short)(ph[2] >> 16)));
                pl[2] = pack2(r, r2);
                r  = s[j0+1][2] - __bfloat162float(__ushort_as_bfloat16((unsigned short)(ph[3] & 0xffff)));
                r2 = s[j0+1][3] - __bfloat162float(__ushort_as_bfloat16((unsigned short)(ph[3] >> 16)));
                pl[3] = pack2(r, r2);
            }
#pragma unroll
            for (int dj = 0; dj < 8; dj++) {
                int bb = (dj*8 + g) * 72 + kc*16 + 2*t;
                unsigned vh[2], vl[2];
                vh[0] = *reinterpret_cast<const unsigned*>(&sVh[bb]);
                vh[1] = *reinterpret_cast<const unsigned*>(&sVh[bb + 8]);
                vl[0] = *reinterpret_cast<const unsigned*>(&sVl[bb]);
                vl[1] = *reinterpret_cast<const unsigned*>(&sVl[bb + 8]);
                mma16816(o[dj], ph, vh);
                mma16816(o[dj], ph, vl);
                mma16816(o[dj], pl, vh);
            }
        }
        stage ^= 1;
    }

    // ---- epilogue: normalize + split hi/lo directly ----
    const float inv0 = 1.f / l0, inv1 = 1.f / l1;
#pragma unroll
    for (int dj = 0; dj < 8; dj++) {
        int col = h*64 + dj*8 + 2*t;
        store_split2(outh, outl, (size_t)row0 * CDIM + col,
                     o[dj][0]*inv0, o[dj][1]*inv0);
        store_split2(outh, outl, (size_t)row1 * CDIM + col,
                     o[dj][2]*inv1, o[dj][3]*inv1);
    }
}

// ---------------------------------------------------------------------------
extern "C" void kernel_launch(void* const* d_in, const int* in_sizes, int n_in,
                              void* d_out, int out_size)
{
    const float* x = nullptr; const float* w_qkv = nullptr;
    const float* w_proj = nullptr; const float* b_proj = nullptr;
    for (int i = 0; i < n_in; i++) {
        switch (in_sizes[i]) {
            case SEQ * CDIM:   x      = (const float*)d_in[i]; break;
            case QKV3 * CDIM:  w_qkv  = (const float*)d_in[i]; break;
            case CDIM * CDIM:  w_proj = (const float*)d_in[i]; break;
            case CDIM:         b_proj = (const float*)d_in[i]; break;
        }
    }
    float* out = (float*)d_out;

    float *qkv;
    __nv_bfloat16 *xh,*xl,*wqh,*wql,*wph,*wpl,*qh,*ql,*kh,*kl,*vth,*vtl,*ah,*al;
    cudaGetSymbolAddress((void**)&qkv, g_qkv);
    cudaGetSymbolAddress((void**)&xh, g_xh);   cudaGetSymbolAddress((void**)&xl, g_xl);
    cudaGetSymbolAddress((void**)&wqh, g_wqh); cudaGetSymbolAddress((void**)&wql, g_wql);
    cudaGetSymbolAddress((void**)&wph, g_wph); cudaGetSymbolAddress((void**)&wpl, g_wpl);
    cudaGetSymbolAddress((void**)&qh, g_qh);   cudaGetSymbolAddress((void**)&ql, g_ql);
    cudaGetSymbolAddress((void**)&kh, g_kh);   cudaGetSymbolAddress((void**)&kl, g_kl);
    cudaGetSymbolAddress((void**)&vth, g_vth); cudaGetSymbolAddress((void**)&vtl, g_vtl);
    cudaGetSymbolAddress((void**)&ah, g_ah);   cudaGetSymbolAddress((void**)&al, g_al);

    const int gemm_smem = 2 * G_STG * (int)sizeof(__nv_bfloat16);          // 81920
    const int attn_smem = (A_Q + 2 * A_STG) * (int)sizeof(__nv_bfloat16);  // 110592
    cudaFuncSetAttribute(gemm_nt_mma<0>, cudaFuncAttributeMaxDynamicSharedMemorySize, gemm_smem);
    cudaFuncSetAttribute(gemm_nt_mma<1>, cudaFuncAttributeMaxDynamicSharedMemorySize, gemm_smem);
    cudaFuncSetAttribute(attn_mma, cudaFuncAttributeMaxDynamicSharedMemorySize, attn_smem);

    // split inputs and weights
    split_plain<<<(SEQ*CDIM/4 + 255)/256, 256>>>(x, xh, xl, SEQ*CDIM/4);
    split_plain<<<(QKV3*CDIM/4 + 255)/256, 256>>>(w_qkv, wqh, wql, QKV3*CDIM/4);
    split_plain<<<(CDIM*CDIM/4 + 255)/256, 256>>>(w_proj, wph, wpl, CDIM*CDIM/4);

    // 1) QKV projection with fused Q/K split epilogue (V -> fp32 qkv buffer)
    gemm_nt_mma<0><<<dim3(QKV3/128, SEQ/128), 256, gemm_smem>>>(
        xh, xl, wqh, wql, nullptr, qkv, qh, ql, kh, kl, SEQ, QKV3, CDIM);

    // 2) V transpose + split (reads fp32 V third of qkv)
    split_v_trans<<<dim3(SEQ/64, HEADS), 256>>>(qkv, vth, vtl);

    // 3) attention (log2-domain scores; writes hi/lo directly)
    attn_mma<<<dim3(SEQ/128, HEADS), 256, attn_smem>>>(
        qh, ql, kh, kl, vth, vtl, ah, al);

    // 4) output projection
    gemm_nt_mma<1><<<dim3(CDIM/128, SEQ/128), 256, gemm_smem>>>(
        ah, al, wph, wpl, b_proj, out, nullptr, nullptr, nullptr, nullptr,
        SEQ, CDIM, CDIM);
}

// round 14
// speedup vs baseline: 1.5502x; 1.5502x over previous
#include <cuda_runtime.h>
#include <cuda_bf16.h>
#include <cstdint>

// Problem: B=1, N=4096, H=16, D=64, C=1024
static constexpr int SEQ   = 4096;
static constexpr int CDIM  = 1024;
static constexpr int QKV3  = 3 * CDIM;   // 3072
static constexpr int HEADS = 16;
static constexpr float SCALE = 0.125f;   // 64^-0.5

// ---------------------------------------------------------------------------
// Scratch (device globals; no allocations allowed)
// ---------------------------------------------------------------------------
__device__ float g_qkv [SEQ * QKV3];      // fp32 qkv

// GEMM operand buffers: k-dim quartet-permuted (see perm16)
__device__ __nv_bfloat16 g_xh[SEQ * CDIM],  g_xl[SEQ * CDIM];
__device__ __nv_bfloat16 g_wqh[QKV3 * CDIM], g_wql[QKV3 * CDIM];
__device__ __nv_bfloat16 g_wph[CDIM * CDIM], g_wpl[CDIM * CDIM];
// attention buffers: NOT permuted. per-head contiguous: [h][n][64]
__device__ __nv_bfloat16 g_qh[HEADS * SEQ * 64], g_ql[HEADS * SEQ * 64];
__device__ __nv_bfloat16 g_kh[HEADS * SEQ * 64], g_kl[HEADS * SEQ * 64];
// V transposed: [h][d][n]
__device__ __nv_bfloat16 g_vth[HEADS * 64 * SEQ], g_vtl[HEADS * 64 * SEQ];
// attention output split (k-dim quartet-permuted for proj GEMM)
__device__ __nv_bfloat16 g_ah[SEQ * CDIM], g_al[SEQ * CDIM];

// ---------------------------------------------------------------------------
// Helpers
// ---------------------------------------------------------------------------
__device__ __forceinline__ void mma16816(float* c, const unsigned* a, const unsigned* b)
{
    asm volatile(
        "mma.sync.aligned.m16n8k16.row.col.f32.bf16.bf16.f32 "
        "{%0,%1,%2,%3}, {%4,%5,%6,%7}, {%8,%9}, {%0,%1,%2,%3};"
        : "+f"(c[0]), "+f"(c[1]), "+f"(c[2]), "+f"(c[3])
        : "r"(a[0]), "r"(a[1]), "r"(a[2]), "r"(a[3]), "r"(b[0]), "r"(b[1]));
}

__device__ __forceinline__ unsigned pack2(float x, float y)
{
    unsigned lo = (unsigned)__bfloat16_as_ushort(__float2bfloat16_rn(x));
    unsigned hi = (unsigned)__bfloat16_as_ushort(__float2bfloat16_rn(y));
    return lo | (hi << 16);
}

__device__ __forceinline__ void split1(float x, unsigned short& h, unsigned short& l)
{
    __nv_bfloat16 hb = __float2bfloat16_rn(x);
    __nv_bfloat16 lb = __float2bfloat16_rn(x - __bfloat162float(hb));
    h = __bfloat16_as_ushort(hb);
    l = __bfloat16_as_ushort(lb);
}

// quartet permutation within 16-element k-groups: logical even element e ->
// storage position so that {2t,2t+1,2t+8,2t+9} sit contiguously at 4t.
// pairs: e(mod16) in {0,2,4,6} -> 4*(e/2); in {8,10,12,14} -> 4*((e-8)/2)+2
__device__ __forceinline__ int perm16(int e)   // e even
{
    int r = e & 15;
    int pos = (r < 8) ? ((r >> 1) << 2) : ((((r - 8) >> 1) << 2) + 2);
    return (e & ~15) | pos;
}

__device__ __forceinline__ void cp16(void* s, const void* g)
{
    unsigned sa = (unsigned)__cvta_generic_to_shared(s);
    asm volatile("cp.async.cg.shared.global [%0], [%1], 16;" :: "r"(sa), "l"(g));
}
__device__ __forceinline__ void cp_commit()
{
    asm volatile("cp.async.commit_group;");
}
__device__ __forceinline__ void cp_wait_all()
{
    asm volatile("cp.async.wait_group 0;");
}

// ---------------------------------------------------------------------------
// Elementwise hi/lo split with quartet permutation of the k index.
// Each thread handles 4 consecutive elements = 2 pairs.
// ---------------------------------------------------------------------------
__global__ void split_plain(const float* __restrict__ in,
                            __nv_bfloat16* __restrict__ hi,
                            __nv_bfloat16* __restrict__ lo, int n4)
{
    int i = blockIdx.x * blockDim.x + threadIdx.x;
    if (i >= n4) return;
    float4 v = reinterpret_cast<const float4*>(in)[i];
    int k0 = 4 * i;
    unsigned short h0,h1,h2,h3,l0,l1,l2,l3;
    split1(v.x,h0,l0); split1(v.y,h1,l1); split1(v.z,h2,l2); split1(v.w,h3,l3);
    int d0 = perm16(k0);
    int d1 = perm16(k0 + 2);
    *reinterpret_cast<unsigned*>(&hi[d0]) = (unsigned)h0 | ((unsigned)h1 << 16);
    *reinterpret_cast<unsigned*>(&hi[d1]) = (unsigned)h2 | ((unsigned)h3 << 16);
    *reinterpret_cast<unsigned*>(&lo[d0]) = (unsigned)l0 | ((unsigned)l1 << 16);
    *reinterpret_cast<unsigned*>(&lo[d1]) = (unsigned)l2 | ((unsigned)l3 << 16);
}

// qkv fp32 [n][3C] -> Q,K hi/lo per-head [h][n][64]  (UNpermuted)
__global__ void split_qk(const float* __restrict__ qkv,
                         __nv_bfloat16* __restrict__ qh, __nv_bfloat16* __restrict__ ql,
                         __nv_bfloat16* __restrict__ kh, __nv_bfloat16* __restrict__ kl)
{
    int idx = blockIdx.x * 256 + threadIdx.x;      // 16*4096*16 = 1M
    int h  = idx >> 16;
    int r  = idx & 65535;
    int n  = r >> 4;
    int d4 = (r & 15) * 4;
    const float4 q = *reinterpret_cast<const float4*>(&qkv[(size_t)n * QKV3 + h * 64 + d4]);
    const float4 k = *reinterpret_cast<const float4*>(&qkv[(size_t)n * QKV3 + CDIM + h * 64 + d4]);
    size_t o = ((size_t)h << 18) + (size_t)n * 64 + d4;
    unsigned short a0,a1,a2,a3,b0,b1,b2,b3;
    uint2 u;
    split1(q.x,a0,b0); split1(q.y,a1,b1); split1(q.z,a2,b2); split1(q.w,a3,b3);
    u.x = (unsigned)a0 | ((unsigned)a1<<16); u.y = (unsigned)a2 | ((unsigned)a3<<16);
    *reinterpret_cast<uint2*>(&qh[o]) = u;
    u.x = (unsigned)b0 | ((unsigned)b1<<16); u.y = (unsigned)b2 | ((unsigned)b3<<16);
    *reinterpret_cast<uint2*>(&ql[o]) = u;
    split1(k.x,a0,b0); split1(k.y,a1,b1); split1(k.z,a2,b2); split1(k.w,a3,b3);
    u.x = (unsigned)a0 | ((unsigned)a1<<16); u.y = (unsigned)a2 | ((unsigned)a3<<16);
    *reinterpret_cast<uint2*>(&kh[o]) = u;
    u.x = (unsigned)b0 | ((unsigned)b1<<16); u.y = (unsigned)b2 | ((unsigned)b3<<16);
    *reinterpret_cast<uint2*>(&kl[o]) = u;
}

// V: qkv fp32 -> transposed hi/lo [h][d][n]  (UNpermuted)
__global__ void split_v_trans(const float* __restrict__ qkv,
                              __nv_bfloat16* __restrict__ vth,
                              __nv_bfloat16* __restrict__ vtl)
{
    __shared__ float tile[64][65];
    const int h  = blockIdx.y;
    const int nb = blockIdx.x * 64;
    const int tid = threadIdx.x;
#pragma unroll
    for (int it = 0; it < 4; it++) {
        int slot = tid + it * 256;          // 0..1023
        int row  = slot >> 4;               // n within tile
        int d4   = (slot & 15) * 4;
        float4 v = *reinterpret_cast<const float4*>(
            &qkv[(size_t)(nb + row) * QKV3 + 2 * CDIM + h * 64 + d4]);
        tile[row][d4+0] = v.x; tile[row][d4+1] = v.y;
        tile[row][d4+2] = v.z; tile[row][d4+3] = v.w;
    }
    __syncthreads();
    const int d  = tid >> 2;
    const int n0 = (tid & 3) * 16;
    size_t base = ((size_t)h << 18) + (size_t)d * SEQ + nb + n0;
#pragma unroll
    for (int seg = 0; seg < 4; seg++) {
        unsigned short hh[4], ll[4];
#pragma unroll
        for (int j = 0; j < 4; j++) split1(tile[n0 + seg*4 + j][d], hh[j], ll[j]);
        uint2 u;
        u.x = (unsigned)hh[0] | ((unsigned)hh[1]<<16); u.y = (unsigned)hh[2] | ((unsigned)hh[3]<<16);
        *reinterpret_cast<uint2*>(&vth[base + seg*4]) = u;
        u.x = (unsigned)ll[0] | ((unsigned)ll[1]<<16); u.y = (unsigned)ll[2] | ((unsigned)ll[3]<<16);
        *reinterpret_cast<uint2*>(&vtl[base + seg*4]) = u;
    }
}

// ---------------------------------------------------------------------------
// Split-bf16 tensor-core GEMM, 2-stage cp.async pipeline, quartet-permuted
// operands -> LDS.64 fragment loads. C[M,N] = A[M,K]*B[N,K]^T (+bias).
// 128x128 block, 8 warps (2m x 4n), warp 64x32, K-tile 32.
// smem row stride 48 bf16 (24 words): conflict-free 16-lane-phase LDS.64.
// ---------------------------------------------------------------------------
static constexpr int G_STG = 4 * 128 * 48;   // bf16 per stage (24576)

template <bool BIAS>
__global__ __launch_bounds__(256, 2) void gemm_nt_mma(
    const __nv_bfloat16* __restrict__ Ah, const __nv_bfloat16* __restrict__ Al,
    const __nv_bfloat16* __restrict__ Bh, const __nv_bfloat16* __restrict__ Bl,
    const float* __restrict__ bias, float* __restrict__ C,
    int M, int N, int K)
{
    extern __shared__ __nv_bfloat16 smem[];

    const int bm = blockIdx.y * 128, bn = blockIdx.x * 128;
    const int tid = threadIdx.x;
    const int warp = tid >> 5, lane = tid & 31;
    const int wm = warp >> 2, wn = warp & 3;      // 2 x 4
    const int g = lane >> 2, t = lane & 3;

    float acc[4][4][4];
#pragma unroll
    for (int mi = 0; mi < 4; mi++)
#pragma unroll
        for (int ni = 0; ni < 4; ni++)
#pragma unroll
            for (int r = 0; r < 4; r++) acc[mi][ni][r] = 0.f;

    auto load_tile = [&](int st, int k0) {
        __nv_bfloat16* sAh = smem + st * G_STG;
        __nv_bfloat16* sAl = sAh + 128*48;
        __nv_bfloat16* sBh = sAh + 2*128*48;
        __nv_bfloat16* sBl = sAh + 3*128*48;
#pragma unroll
        for (int it = 0; it < 2; it++) {
            int slot = tid + it * 256;            // 0..511
            int row  = slot >> 2;                 // 0..127
            int kc   = (slot & 3) * 8;            // 0,8,16,24
            size_t ga = (size_t)(bm + row) * K + k0 + kc;
            size_t gb = (size_t)(bn + row) * K + k0 + kc;
            cp16(&sAh[row*48 + kc], &Ah[ga]);
            cp16(&sAl[row*48 + kc], &Al[ga]);
            cp16(&sBh[row*48 + kc], &Bh[gb]);
            cp16(&sBl[row*48 + kc], &Bl[gb]);
        }
        cp_commit();
    };

    load_tile(0, 0);
    int stage = 0;

    for (int k0 = 0; k0 < K; k0 += 32) {
        cp_wait_all();
        __syncthreads();
        if (k0 + 32 < K) load_tile(stage ^ 1, k0 + 32);

        const __nv_bfloat16* sAh = smem + stage * G_STG;
        const __nv_bfloat16* sAl = sAh + 128*48;
        const __nv_bfloat16* sBh = sAh + 2*128*48;
        const __nv_bfloat16* sBl = sAh + 3*128*48;

#pragma unroll
        for (int kk = 0; kk < 32; kk += 16) {
            // B fragments: one LDS.64 per (ni, array)
            unsigned bh[4][2], bl[4][2];
#pragma unroll
            for (int ni = 0; ni < 4; ni++) {
                int base = (wn*32 + ni*8 + g) * 48 + kk + 4*t;
                uint2 vb = *reinterpret_cast<const uint2*>(&sBh[base]);
                bh[ni][0] = vb.x; bh[ni][1] = vb.y;
                uint2 vl = *reinterpret_cast<const uint2*>(&sBl[base]);
                bl[ni][0] = vl.x; bl[ni][1] = vl.y;
            }
#pragma unroll
            for (int mi = 0; mi < 4; mi++) {
                // A fragments: two LDS.64 per array (rows g and g+8)
                int base = (wm*64 + mi*16 + g) * 48 + kk + 4*t;
                unsigned ah[4], al[4];
                {
                    uint2 r0 = *reinterpret_cast<const uint2*>(&sAh[base]);
                    uint2 r1 = *reinterpret_cast<const uint2*>(&sAh[base + 8*48]);
                    ah[0] = r0.x; ah[1] = r1.x; ah[2] = r0.y; ah[3] = r1.y;
                }
                {
                    uint2 r0 = *reinterpret_cast<const uint2*>(&sAl[base]);
                    uint2 r1 = *reinterpret_cast<const uint2*>(&sAl[base + 8*48]);
                    al[0] = r0.x; al[1] = r1.x; al[2] = r0.y; al[3] = r1.y;
                }
#pragma unroll
                for (int ni = 0; ni < 4; ni++) {
                    mma16816(acc[mi][ni], ah, bh[ni]);
                    mma16816(acc[mi][ni], ah, bl[ni]);
                    mma16816(acc[mi][ni], al, bh[ni]);
                }
            }
        }
        stage ^= 1;
    }

#pragma unroll
    for (int mi = 0; mi < 4; mi++) {
        int r0 = bm + wm*64 + mi*16 + g;
#pragma unroll
        for (int ni = 0; ni < 4; ni++) {
            int col = bn + wn*32 + ni*8 + 2*t;
            float b0 = 0.f, b1 = 0.f;
            if (BIAS) { b0 = bias[col]; b1 = bias[col + 1]; }
            float2 v0 = {acc[mi][ni][0] + b0, acc[mi][ni][1] + b1};
            float2 v1 = {acc[mi][ni][2] + b0, acc[mi][ni][3] + b1};
            *reinterpret_cast<float2*>(&C[(size_t)r0 * N + col])       = v0;
            *reinterpret_cast<float2*>(&C[(size_t)(r0+8) * N + col])   = v1;
        }
    }
}

// ---------------------------------------------------------------------------
// Flash attention (R8 version, unchanged core): scalar LDS frags + cp.async
// pipeline. Block = 128 q-rows x 1 head, 8 warps, each warp owns 16 rows.
// Epilogue writes hi/lo bf16 with quartet permutation (for proj GEMM).
// ---------------------------------------------------------------------------
static constexpr int A_Q   = 2 * 128 * 72;   // Q hi+lo bf16 (18432)
static constexpr int A_STG = 4 * 64 * 72;    // K/V hi+lo per stage (18432)

__global__ __launch_bounds__(256, 2) void attn_mma(
    const __nv_bfloat16* __restrict__ Qh, const __nv_bfloat16* __restrict__ Ql,
    const __nv_bfloat16* __restrict__ Kh, const __nv_bfloat16* __restrict__ Kl,
    const __nv_bfloat16* __restrict__ Vth, const __nv_bfloat16* __restrict__ Vtl,
    __nv_bfloat16* __restrict__ outh, __nv_bfloat16* __restrict__ outl)
{
    extern __shared__ __nv_bfloat16 sm[];
    __nv_bfloat16* sQh = sm;               // [128][72]
    __nv_bfloat16* sQl = sm + 128*72;
    __nv_bfloat16* kvb = sm + A_Q;

    const int qi = gridDim.x - 1 - blockIdx.x;   // reverse for causal balance
    const int h  = blockIdx.y;
    const int qbase = qi * 128;
    const int tid = threadIdx.x;
    const int warp = tid >> 5, lane = tid & 31;
    const int g = lane >> 2, t = lane & 3;
    const size_t hoff = (size_t)h << 18;         // h * 4096 * 64

    auto load_kv = [&](int st, int jt) {
        __nv_bfloat16* sKh = kvb + st * A_STG;
        __nv_bfloat16* sKl = sKh + 64*72;
        __nv_bfloat16* sVh = sKh + 2*64*72;
        __nv_bfloat16* sVl = sKh + 3*64*72;
        const int kb = jt * 64;
#pragma unroll
        for (int it = 0; it < 2; it++) {
            int slot = tid + it * 256;    // 0..511
            int row  = slot >> 3;         // 0..63
            int kc   = (slot & 7) * 8;
            size_t gk = hoff + (size_t)(kb + row) * 64 + kc;
            size_t gv = hoff + (size_t)row * SEQ + kb + kc;
            cp16(&sKh[row*72 + kc], &Kh[gk]);
            cp16(&sKl[row*72 + kc], &Kl[gk]);
            cp16(&sVh[row*72 + kc], &Vth[gv]);
            cp16(&sVl[row*72 + kc], &Vtl[gv]);
        }
        cp_commit();
    };

#pragma unroll
    for (int it = 0; it < 4; it++) {
        int slot = tid + it * 256;        // 0..1023
        int row  = slot >> 3;             // 0..127
        int kc   = (slot & 7) * 8;        // 0..56
        size_t gq = hoff + (size_t)(qbase + row) * 64 + kc;
        cp16(&sQh[row*72 + kc], &Qh[gq]);
        cp16(&sQl[row*72 + kc], &Ql[gq]);
    }
    cp_commit();
    load_kv(0, 0);
    int stage = 0;

    float o[8][4];
#pragma unroll
    for (int j = 0; j < 8; j++)
#pragma unroll
        for (int r = 0; r < 4; r++) o[j][r] = 0.f;
    float m0 = -1e30f, m1 = -1e30f, l0 = 0.f, l1 = 0.f;

    const int row0 = qbase + warp*16 + g;
    const int row1 = row0 + 8;
    const int jt_max = 2*qi + 1;

    for (int jt = 0; jt <= jt_max; jt++) {
        cp_wait_all();
        __syncthreads();
        if (jt < jt_max) load_kv(stage ^ 1, jt + 1);

        const __nv_bfloat16* sKh = kvb + stage * A_STG;
        const __nv_bfloat16* sKl = sKh + 64*72;
        const __nv_bfloat16* sVh = sKh + 2*64*72;
        const __nv_bfloat16* sVl = sKh + 3*64*72;
        const int kb = jt * 64;

        // ---- S = Q K^T ----
        float s[8][4];
#pragma unroll
        for (int j = 0; j < 8; j++)
#pragma unroll
            for (int r = 0; r < 4; r++) s[j][r] = 0.f;

#pragma unroll
        for (int kc = 0; kc < 64; kc += 16) {
            int ab = (warp*16 + g) * 72 + kc + 2*t;
            unsigned qh[4], ql[4];
            qh[0] = *reinterpret_cast<const unsigned*>(&sQh[ab]);
            qh[1] = *reinterpret_cast<const unsigned*>(&sQh[ab + 8*72]);
            qh[2] = *reinterpret_cast<const unsigned*>(&sQh[ab + 8]);
            qh[3] = *reinterpret_cast<const unsigned*>(&sQh[ab + 8*72 + 8]);
            ql[0] = *reinterpret_cast<const unsigned*>(&sQl[ab]);
            ql[1] = *reinterpret_cast<const unsigned*>(&sQl[ab + 8*72]);
            ql[2] = *reinterpret_cast<const unsigned*>(&sQl[ab + 8]);
            ql[3] = *reinterpret_cast<const unsigned*>(&sQl[ab + 8*72 + 8]);
#pragma unroll
            for (int j = 0; j < 8; j++) {
                int bb = (j*8 + g) * 72 + kc + 2*t;
                unsigned kh[2], kl[2];
                kh[0] = *reinterpret_cast<const unsigned*>(&sKh[bb]);
                kh[1] = *reinterpret_cast<const unsigned*>(&sKh[bb + 8]);
                kl[0] = *reinterpret_cast<const unsigned*>(&sKl[bb]);
                kl[1] = *reinterpret_cast<const unsigned*>(&sKl[bb + 8]);
                mma16816(s[j], qh, kh);
                mma16816(s[j], qh, kl);
                mma16816(s[j], ql, kh);
            }
        }

        // ---- scale + causal mask ----
        const bool need_mask = (jt >= 2*qi);
#pragma unroll
        for (int j = 0; j < 8; j++) {
            int c0 = kb + j*8 + 2*t;
            s[j][0] *= SCALE; s[j][1] *= SCALE; s[j][2] *= SCALE; s[j][3] *= SCALE;
            if (need_mask) {
                if (c0     > row0) s[j][0] = -1e30f;
                if (c0 + 1 > row0) s[j][1] = -1e30f;
                if (c0     > row1) s[j][2] = -1e30f;
                if (c0 + 1 > row1) s[j][3] = -1e30f;
            }
        }

        // ---- online softmax ----
        float mx0 = -1e30f, mx1 = -1e30f;
#pragma unroll
        for (int j = 0; j < 8; j++) {
            mx0 = fmaxf(mx0, fmaxf(s[j][0], s[j][1]));
            mx1 = fmaxf(mx1, fmaxf(s[j][2], s[j][3]));
        }
        mx0 = fmaxf(mx0, __shfl_xor_sync(0xffffffffu, mx0, 1));
        mx0 = fmaxf(mx0, __shfl_xor_sync(0xffffffffu, mx0, 2));
        mx1 = fmaxf(mx1, __shfl_xor_sync(0xffffffffu, mx1, 1));
        mx1 = fmaxf(mx1, __shfl_xor_sync(0xffffffffu, mx1, 2));

        const float mn0 = fmaxf(m0, mx0), mn1 = fmaxf(m1, mx1);
        const float a0 = __expf(m0 - mn0), a1 = __expf(m1 - mn1);
        float sum0 = 0.f, sum1 = 0.f;
#pragma unroll
        for (int j = 0; j < 8; j++) {
            s[j][0] = __expf(s[j][0] - mn0); sum0 += s[j][0];
            s[j][1] = __expf(s[j][1] - mn0); sum0 += s[j][1];
            s[j][2] = __expf(s[j][2] - mn1); sum1 += s[j][2];
            s[j][3] = __expf(s[j][3] - mn1); sum1 += s[j][3];
        }
        sum0 += __shfl_xor_sync(0xffffffffu, sum0, 1);
        sum0 += __shfl_xor_sync(0xffffffffu, sum0, 2);
        sum1 += __shfl_xor_sync(0xffffffffu, sum1, 1);
        sum1 += __shfl_xor_sync(0xffffffffu, sum1, 2);
        l0 = l0 * a0 + sum0;  m0 = mn0;
        l1 = l1 * a1 + sum1;  m1 = mn1;
#pragma unroll
        for (int j = 0; j < 8; j++) {
            o[j][0] *= a0; o[j][1] *= a0;
            o[j][2] *= a1; o[j][3] *= a1;
        }

        // ---- O += P V : P frags straight from S registers ----
#pragma unroll
        for (int kc = 0; kc < 4; kc++) {              // 16 keys each
            const int j0 = 2*kc;
            unsigned ph[4], pl[4];
            ph[0] = pack2(s[j0][0],   s[j0][1]);
            ph[1] = pack2(s[j0][2],   s[j0][3]);
            ph[2] = pack2(s[j0+1][0], s[j0+1][1]);
            ph[3] = pack2(s[j0+1][2], s[j0+1][3]);
            {
                float r, r2;
                r  = s[j0][0] - __bfloat162float(__ushort_as_bfloat16((unsigned short)(ph[0] & 0xffff)));
                r2 = s[j0][1] - __bfloat162float(__ushort_as_bfloat16((unsigned short)(ph[0] >> 16)));
                pl[0] = pack2(r, r2);
                r  = s[j0][2] - __bfloat162float(__ushort_as_bfloat16((unsigned short)(ph[1] & 0xffff)));
                r2 = s[j0][3] - __bfloat162float(__ushort_as_bfloat16((unsigned short)(ph[1] >> 16)));
                pl[1] = pack2(r, r2);
                r  = s[j0+1][0] - __bfloat162float(__ushort_as_bfloat16((unsigned short)(ph[2] & 0xffff)));
                r2 = s[j0+1][1] - __bfloat162float(__ushort_as_bfloat16((unsigned short)(ph[2] >> 16)));
                pl[2] = pack2(r, r2);
                r  = s[j0+1][2] - __bfloat162float(__ushort_as_bfloat16((unsigned short)(ph[3] & 0xffff)));
                r2 = s[j0+1][3] - __bfloat162float(__ushort_as_bfloat16((unsigned short)(ph[3] >> 16)));
                pl[3] = pack2(r, r2);
            }
#pragma unroll
            for (int dj = 0; dj < 8; dj++) {
                int bb = (dj*8 + g) * 72 + kc*16 + 2*t;
                unsigned vh[2], vl[2];
                vh[0] = *reinterpret_cast<const unsigned*>(&sVh[bb]);
                vh[1] = *reinterpret_cast<const unsigned*>(&sVh[bb + 8]);
                vl[0] = *reinterpret_cast<const unsigned*>(&sVl[bb]);
                vl[1] = *reinterpret_cast<const unsigned*>(&sVl[bb + 8]);
                mma16816(o[dj], ph, vh);
                mma16816(o[dj], ph, vl);
                mma16816(o[dj], pl, vh);
            }
        }
        stage ^= 1;
    }

    // ---- epilogue: normalize + split hi/lo, quartet-permuted k positions ----
    const float inv0 = 1.f / l0, inv1 = 1.f / l1;
#pragma unroll
    for (int dj = 0; dj < 8; dj++) {
        int col = h*64 + dj*8 + 2*t;
        int pc  = perm16(col);
        float v00 = o[dj][0]*inv0, v01 = o[dj][1]*inv0;
        float v10 = o[dj][2]*inv1, v11 = o[dj][3]*inv1;
        unsigned short h0,h1,l0s,l1s;
        split1(v00, h0, l0s); split1(v01, h1, l1s);
        *reinterpret_cast<unsigned*>(&outh[(size_t)row0 * CDIM + pc]) =
            (unsigned)h0 | ((unsigned)h1 << 16);
        *reinterpret_cast<unsigned*>(&outl[(size_t)row0 * CDIM + pc]) =
            (unsigned)l0s | ((unsigned)l1s << 16);
        split1(v10, h0, l0s); split1(v11, h1, l1s);
        *reinterpret_cast<unsigned*>(&outh[(size_t)row1 * CDIM + pc]) =
            (unsigned)h0 | ((unsigned)h1 << 16);
        *reinterpret_cast<unsigned*>(&outl[(size_t)row1 * CDIM + pc]) =
            (unsigned)l0s | ((unsigned)l1s << 16);
    }
}

// ---------------------------------------------------------------------------
extern "C" void kernel_launch(void* const* d_in, const int* in_sizes, int n_in,
                              void* d_out, int out_size)
{
    const float* x = nullptr; const float* w_qkv = nullptr;
    const float* w_proj = nullptr; const float* b_proj = nullptr;
    for (int i = 0; i < n_in; i++) {
        switch (in_sizes[i]) {
            case SEQ * CDIM:   x      = (const float*)d_in[i]; break;
            case QKV3 * CDIM:  w_qkv  = (const float*)d_in[i]; break;
            case CDIM * CDIM:  w_proj = (const float*)d_in[i]; break;
            case CDIM:         b_proj = (const float*)d_in[i]; break;
        }
    }
    float* out = (float*)d_out;

    float *qkv;
    __nv_bfloat16 *xh,*xl,*wqh,*wql,*wph,*wpl,*qh,*ql,*kh,*kl,*vth,*vtl,*ah,*al;
    cudaGetSymbolAddress((void**)&qkv, g_qkv);
    cudaGetSymbolAddress((void**)&xh, g_xh);   cudaGetSymbolAddress((void**)&xl, g_xl);
    cudaGetSymbolAddress((void**)&wqh, g_wqh); cudaGetSymbolAddress((void**)&wql, g_wql);
    cudaGetSymbolAddress((void**)&wph, g_wph); cudaGetSymbolAddress((void**)&wpl, g_wpl);
    cudaGetSymbolAddress((void**)&qh, g_qh);   cudaGetSymbolAddress((void**)&ql, g_ql);
    cudaGetSymbolAddress((void**)&kh, g_kh);   cudaGetSymbolAddress((void**)&kl, g_kl);
    cudaGetSymbolAddress((void**)&vth, g_vth); cudaGetSymbolAddress((void**)&vtl, g_vtl);
    cudaGetSymbolAddress((void**)&ah, g_ah);   cudaGetSymbolAddress((void**)&al, g_al);

    const int gemm_smem = 2 * G_STG * (int)sizeof(__nv_bfloat16);          // 98304
    const int attn_smem = (A_Q + 2 * A_STG) * (int)sizeof(__nv_bfloat16);  // 110592
    cudaFuncSetAttribute(gemm_nt_mma<false>, cudaFuncAttributeMaxDynamicSharedMemorySize, gemm_smem);
    cudaFuncSetAttribute(gemm_nt_mma<true>,  cudaFuncAttributeMaxDynamicSharedMemorySize, gemm_smem);
    cudaFuncSetAttribute(attn_mma, cudaFuncAttributeMaxDynamicSharedMemorySize, attn_smem);

    // split inputs and weights (quartet-permuted k)
    split_plain<<<(SEQ*CDIM/4 + 255)/256, 256>>>(x, xh, xl, SEQ*CDIM/4);
    split_plain<<<(QKV3*CDIM/4 + 255)/256, 256>>>(w_qkv, wqh, wql, QKV3*CDIM/4);
    split_plain<<<(CDIM*CDIM/4 + 255)/256, 256>>>(w_proj, wph, wpl, CDIM*CDIM/4);

    // 1) QKV projection
    gemm_nt_mma<false><<<dim3(QKV3/128, SEQ/128), 256, gemm_smem>>>(
        xh, xl, wqh, wql, nullptr, qkv, SEQ, QKV3, CDIM);

    // 2) head-layout splits (unpermuted)
    split_qk<<<HEADS*SEQ*16/256, 256>>>(qkv, qh, ql, kh, kl);
    split_v_trans<<<dim3(SEQ/64, HEADS), 256>>>(qkv, vth, vtl);

    // 3) attention (epilogue writes permuted hi/lo)
    attn_mma<<<dim3(SEQ/128, HEADS), 256, attn_smem>>>(
        qh, ql, kh, kl, vth, vtl, ah, al);

    // 4) output projection
    gemm_nt_mma<true><<<dim3(CDIM/128, SEQ/128), 256, gemm_smem>>>(
        ah, al, wph, wpl, b_proj, out, SEQ, CDIM, CDIM);
}